// round 7
// baseline (speedup 1.0000x reference)
#include <cuda_runtime.h>
#include <cuda_fp16.h>
#include <math.h>

#define BATCH 32
#define T     1024
#define DIM   64
#define NW    8                 // DP warps per batch (128 rows each)
#define NCH   76                // chunks of 16 steps: 1216 steps (need 1213)
#define SPAD  1248              // NCH*16 + 32 FIFO pad
#define HANDW 1220              // handoff row width (halves), even
#define SRMAX 221               // epilogue s-rows per tile: 31+127+62 + 1

// Scratch: fp16 cost^2, skew-slotted: g_cst[((b*NW+w)*SPAD + s)*128 + i]
// holds cost[128w + i][s - phi(i)], phi(i) = 6*(i>>2) + (i&3). Invalid = +INF.
__device__ __half g_cst[(size_t)BATCH * NW * SPAD * 128];
__device__ float g_na[BATCH * T];
__device__ float g_nb[BATCH * T];
__device__ float g_dists[BATCH];

__device__ __forceinline__ unsigned hmin2u(unsigned a, unsigned b) {
    __half2 r = __hmin2(*reinterpret_cast<__half2*>(&a), *reinterpret_cast<__half2*>(&b));
    return *reinterpret_cast<unsigned*>(&r);
}
__device__ __forceinline__ unsigned hmax2u(unsigned a, unsigned b) {
    __half2 r = __hmax2(*reinterpret_cast<__half2*>(&a), *reinterpret_cast<__half2*>(&b));
    return *reinterpret_cast<unsigned*>(&r);
}

// ---------------------------------------------------------------------------
__global__ __launch_bounds__(256) void norm_kernel(const float* __restrict__ a,
                                                   const float* __restrict__ b) {
    int gw   = blockIdx.x * 8 + (threadIdx.x >> 5);
    int lane = threadIdx.x & 31;
    int which = gw >> 15;
    int row   = gw & 32767;
    const float* src = (which ? b : a) + (size_t)row * DIM + lane * 2;
    float2 v = *(const float2*)src;
    float s = v.x * v.x + v.y * v.y;
#pragma unroll
    for (int o = 16; o; o >>= 1) s += __shfl_xor_sync(0xffffffffu, s, o);
    if (lane == 0) (which ? g_nb : g_na)[row] = s;
}

// ---------------------------------------------------------------------------
// Fill whole scratch with +INF (cost_kernel then overwrites valid cells).
// ---------------------------------------------------------------------------
__global__ __launch_bounds__(256) void fill_kernel() {
    const int U = SPAD * 128 / 8;                    // uint4 per (b,w) unit
    uint4* p = ((uint4*)g_cst) + (size_t)blockIdx.x * U;
    uint4 v; v.x = v.y = v.z = v.w = 0x7C007C00u;
    for (int k = threadIdx.x; k < U; k += 256) p[k] = v;
}

// ---------------------------------------------------------------------------
// Cost kernel: 128(i) x 32(j) tile, 128 threads, 8x4 fp32 micro-tile.
// Epilogue emits fp16 to the skew-slotted layout.
// ---------------------------------------------------------------------------
__global__ __launch_bounds__(128) void cost_kernel(const float* __restrict__ A,
                                                   const float* __restrict__ B) {
    __shared__ float As[128 * 65];    // reused as half Ch[128][34]
    __shared__ float Bs[32 * 65];

    const int w  = blockIdx.x;
    const int j0 = blockIdx.y * 32;
    const int b  = blockIdx.z;
    const int tid = threadIdx.x;
    const int tx = tid & 7;
    const int ty = tid >> 3;

    const float* Ab = A + ((size_t)b * T + w * 128) * DIM;
    const float* Bb = B + ((size_t)b * T + j0) * DIM;

    for (int v = tid; v < 128 * 16; v += 128) {
        int i = v >> 4, kq = v & 15;
        float4 va = *(const float4*)(Ab + (size_t)i * DIM + kq * 4);
        int base = i * 65 + kq * 4;
        As[base + 0] = va.x; As[base + 1] = va.y; As[base + 2] = va.z; As[base + 3] = va.w;
    }
    for (int v = tid; v < 32 * 16; v += 128) {
        int j = v >> 4, kq = v & 15;
        float4 vb = *(const float4*)(Bb + (size_t)j * DIM + kq * 4);
        int base = j * 65 + kq * 4;
        Bs[base + 0] = vb.x; Bs[base + 1] = vb.y; Bs[base + 2] = vb.z; Bs[base + 3] = vb.w;
    }
    __syncthreads();

    float acc[8][4];
#pragma unroll
    for (int r = 0; r < 8; r++)
#pragma unroll
        for (int c = 0; c < 4; c++) acc[r][c] = 0.f;

#pragma unroll 4
    for (int k = 0; k < DIM; k++) {
        float ar[8], br[4];
#pragma unroll
        for (int r = 0; r < 8; r++) ar[r] = As[(ty * 8 + r) * 65 + k];
#pragma unroll
        for (int c = 0; c < 4; c++) br[c] = Bs[(tx * 4 + c) * 65 + k];
#pragma unroll
        for (int r = 0; r < 8; r++)
#pragma unroll
            for (int c = 0; c < 4; c++) acc[r][c] += ar[r] * br[c];
    }
    __syncthreads();

    __half* Ch = (__half*)As;        // [128][34]
    {
        float nar[8], nbr[4];
        const float* nap = g_na + b * T + w * 128 + ty * 8;
        const float* nbp = g_nb + b * T + j0 + tx * 4;
#pragma unroll
        for (int r = 0; r < 8; r++) nar[r] = nap[r];
#pragma unroll
        for (int c = 0; c < 4; c++) nbr[c] = nbp[c];
#pragma unroll
        for (int r = 0; r < 8; r++)
#pragma unroll
            for (int c = 0; c < 4; c++) {
                float sq = nar[r] + nbr[c] - 2.0f * acc[r][c];
                Ch[(ty * 8 + r) * 34 + (tx * 4 + c)] = __float2half_rn(fmaxf(sq, 1e-12f));
            }
    }
    __syncthreads();

    // Emit: slot s = j + phi(i). sr = s - j0 in [0, SRMAX).
    // One warp per sr row; lanes cover i = ihi-31+lane (contiguous stores).
    const int wid = tid >> 5, lane = tid & 31;
    size_t sbase = ((size_t)(b * NW + w) * SPAD + j0) * 128;
#pragma unroll 1
    for (int it = 0; it < 56; it++) {
        int sr = it * 4 + wid;
        if (sr < SRMAX) {
            int aq = sr / 6, bq = sr - 6 * aq;
            int ihi = 4 * aq + (bq < 3 ? bq : 3);
            if (ihi > 127) ihi = 127;
            int i = ihi - 31 + lane;
            if (i >= 0) {
                int jr = sr - (6 * (i >> 2) + (i & 3));
                if (jr >= 0 && jr < 32)
                    g_cst[sbase + (size_t)sr * 128 + i] = Ch[i * 34 + jr];
            }
        }
    }
}

// ---------------------------------------------------------------------------
// DP kernel: skewed systolic wavefront, fp16x2, extra lane skew E=2 so the
// cross-lane shfl is pipelined 2 steps deep (off the critical chain).
// Chain/step = perm + 2*hmin2 + hmax2 = 16cy. 32-deep LDG FIFO (2x16 arrays;
// fA refills at +32, fB at +48 relative to chunk base -- NOT the same!).
// Cross-warp handoff rows in smem + chunked progress flags.
// ---------------------------------------------------------------------------
__global__ __launch_bounds__(256) void dp_kernel() {
    __shared__ __align__(4) unsigned short hand[(NW + 1) * HANDW];
    __shared__ int progress[NW];

    const int tid = threadIdx.x, w = tid >> 5, lane = tid & 31;
    const int b = blockIdx.x;

    for (int v = tid; v < (NW + 1) * HANDW / 2; v += 256)
        ((unsigned*)hand)[v] = 0x7C007C00u;
    if (lane == 0) progress[w] = 0;
    __syncthreads();

    const unsigned short* hrow = &hand[((w == 0) ? NW : (w - 1)) * HANDW];
    unsigned wrow;   // smem addr; +s*2 -> hand[w][s-189]
    {
        unsigned base;
        asm("{ .reg .u64 t; cvta.to.shared.u64 t, %1; cvt.u32.u64 %0, t; }"
            : "=r"(base) : "l"(&hand[w * HANDW]));
        wrow = base - 378u;
    }

    const __half* cp = g_cst + (size_t)(b * NW + w) * SPAD * 128 + lane * 4;
    uint2 fA[16], fB[16];
#pragma unroll
    for (int q = 0; q < 16; q++) fA[q] = *(const uint2*)(cp + (size_t)q * 128);
#pragma unroll
    for (int q = 0; q < 16; q++) fB[q] = *(const uint2*)(cp + (size_t)(16 + q) * 128);

    const unsigned INF2 = 0x7C007C00u;
    unsigned A = INF2, B = INF2, upAp = INF2, upBp = INF2;
    unsigned sh0 = INF2, sh1 = INF2;
    unsigned hv0 = INF2, hv1 = INF2, hv2 = INF2;
    const bool isl0 = (lane == 0);
    const bool fix0 = (w == 0) && isl0;
    const unsigned p31 = (lane == 31) ? 1u : 0u;
    const __half* cq = cp;

#define DP_STEP(kk, F, ROFF, FIRST)                                            \
    {                                                                          \
        const int s = sbase + (kk);                                            \
        uint2 cw = F[kk];                                                      \
        F[kk] = *(const uint2*)(cq + (size_t)((kk) + (ROFF)) * 128);           \
        unsigned shu = isl0 ? hv0 : sh0;                                       \
        unsigned upA = __byte_perm(shu, A, 0x5432);                            \
        unsigned upB = __byte_perm(A, B, 0x5432);                              \
        unsigned nA = hmax2u(cw.x, hmin2u(hmin2u(upA, upAp), A));              \
        unsigned nB = hmax2u(cw.y, hmin2u(hmin2u(upB, upBp), B));              \
        if ((FIRST) && (kk) == 0) {                                            \
            if (fix0) nA = (nA & 0xFFFF0000u) | (cw.x & 0xFFFFu);              \
        }                                                                      \
        unsigned pr = p31 & (unsigned)(s >= 189);                              \
        asm volatile(                                                          \
            "{ .reg .pred p; setp.ne.u32 p, %0, 0; @p st.shared.u16 [%1], %2; }" \
            :: "r"(pr), "r"(wrow + (unsigned)s * 2),                           \
               "h"((unsigned short)(nB >> 16)));                               \
        unsigned shn = __shfl_up_sync(0xffffffffu, B, 1);                      \
        sh0 = sh1; sh1 = shn;                                                  \
        upAp = upA; upBp = upB;                                                \
        A = nA; B = nB;                                                        \
        hv0 = hv1; hv1 = hv2;                                                  \
        hv2 = ((unsigned)hrow[s + 3]) << 16;                                   \
    }

    for (int td = 0; td < NCH / 2; td++) {
        if (w) {                                     // one wait per 32 steps
            int need = 2 * td + 14; if (need > NCH) need = NCH;
            while (((volatile int*)progress)[w - 1] < need) __nanosleep(32);
            __threadfence_block();
        }
        if (td == 0) {                               // init hand pipeline
            hv0 = ((unsigned)hrow[0]) << 16;
            hv1 = ((unsigned)hrow[1]) << 16;
            hv2 = ((unsigned)hrow[2]) << 16;
        }
        {
            const int sbase = 32 * td;
#pragma unroll
            for (int kk = 0; kk < 16; kk++) DP_STEP(kk, fA, 32, (td == 0))
        }
        __syncwarp();
        __threadfence_block();
        if (lane == 0) ((volatile int*)progress)[w] = 2 * td + 1;
        {
            const int sbase = 32 * td + 16;
#pragma unroll
            for (int kk = 0; kk < 16; kk++) DP_STEP(kk, fB, 48, false)
        }
        __syncwarp();
        __threadfence_block();
        if (lane == 0) ((volatile int*)progress)[w] = 2 * td + 2;
        cq += 32 * 128;
    }
#undef DP_STEP

    __syncthreads();
    if (tid == 0)
        g_dists[b] = sqrtf(__half2float(__ushort_as_half(hand[7 * HANDW + 1023])));
}

// ---------------------------------------------------------------------------
__global__ void finish_kernel(float* __restrict__ out) {
    int t = threadIdx.x;
    float v = g_dists[t];
#pragma unroll
    for (int o = 16; o; o >>= 1) v += __shfl_xor_sync(0xffffffffu, v, o);
    if (t == 0) out[0] = v * (1.0f / BATCH);
}

extern "C" void kernel_launch(void* const* d_in, const int* in_sizes, int n_in,
                              void* d_out, int out_size) {
    const float* pred = (const float*)d_in[0];
    const float* targ = (const float*)d_in[1];
    fill_kernel<<<BATCH * NW, 256>>>();
    norm_kernel<<<(BATCH * T * 2) / 8, 256>>>(pred, targ);
    cost_kernel<<<dim3(NW, T / 32, BATCH), 128>>>(pred, targ);
    dp_kernel<<<BATCH, 256>>>();
    finish_kernel<<<1, 32>>>((float*)d_out);
}

// round 8
// speedup vs baseline: 1.0002x; 1.0002x over previous
#include <cuda_runtime.h>
#include <cuda_fp16.h>
#include <math.h>

#define BATCH 32
#define T     1024
#define DIM   64
#define NW    8                 // DP warps per batch (128 rows each)
#define NCH   76                // chunks of 16 steps: 1216 steps
#define SPAD  1248              // NCH*16 + 32 FIFO pad
#define HANDW 1220              // handoff row width (halves)
#define SRMAX 221               // epilogue s-rows per tile
#define NUNITS 380              // producer units: 116*3 + 32
#define NTILES 8192             // 32 batches * 8 w * 32 jt
#define HAND_BYTES ((NW + 1) * HANDW * 2)     // 21960
#define PROG_OFF   HAND_BYTES                 // progress[8] ints
#define DPUNIT_OFF 22016                      // producer unit smem in DP CTAs
#define UNIT_BYTES ((128 * 65 + 32 * 65) * 4) // 41600
#define SMEM_DYN   (3 * UNIT_BYTES)           // 124800

// fp16 cost^2, skew-slotted: g_cst[((b*NW+w)*SPAD + s)*128 + i] holds
// cost[128w+i][s - phi(i)], phi(i) = 6*(i>>2) + (i&3). Invalid = +INF.
__device__ __half g_cst[(size_t)BATCH * NW * SPAD * 128];
__device__ float g_na[BATCH * T];
__device__ float g_nb[BATCH * T];
__device__ float g_dists[BATCH];
__device__ int   g_flag[BATCH * NW * 32];     // per (b,w,jt) tile-ready flags
__device__ unsigned char g_pairs[256];        // (w*32+jt) sorted by jt+7w

__device__ __forceinline__ unsigned hmin2u(unsigned a, unsigned b) {
    __half2 r = __hmin2(*reinterpret_cast<__half2*>(&a), *reinterpret_cast<__half2*>(&b));
    return *reinterpret_cast<unsigned*>(&r);
}
__device__ __forceinline__ unsigned hmax2u(unsigned a, unsigned b) {
    __half2 r = __hmax2(*reinterpret_cast<__half2*>(&a), *reinterpret_cast<__half2*>(&b));
    return *reinterpret_cast<unsigned*>(&r);
}

#define UBAR(id) asm volatile("bar.sync %0, %1;" :: "r"(id), "r"(128) : "memory")

// ---------------------------------------------------------------------------
__global__ __launch_bounds__(256) void norm_kernel(const float* __restrict__ a,
                                                   const float* __restrict__ b) {
    int gw   = blockIdx.x * 8 + (threadIdx.x >> 5);
    int lane = threadIdx.x & 31;
    int which = gw >> 15;
    int row   = gw & 32767;
    const float* src = (which ? b : a) + (size_t)row * DIM + lane * 2;
    float2 v = *(const float2*)src;
    float s = v.x * v.x + v.y * v.y;
#pragma unroll
    for (int o = 16; o; o >>= 1) s += __shfl_xor_sync(0xffffffffu, s, o);
    if (lane == 0) (which ? g_nb : g_na)[row] = s;
}

// ---------------------------------------------------------------------------
// fill: INF boundary slots [0,189) and [1024,SPAD); zero flags; build order
// table. Middle slots [189,1024) are fully overwritten by producer tiles.
// ---------------------------------------------------------------------------
__global__ __launch_bounds__(256) void fill_kernel() {
    int cta = blockIdx.x;                       // 256 CTAs, one per (b,w)
    unsigned* p32 = (unsigned*)(g_cst + (size_t)cta * SPAD * 128);
    const int NS = 189 + (SPAD - 1024);         // 413 slots
    for (int v = threadIdx.x; v < NS * 64; v += 256) {
        int sr = v >> 6, q = v & 63;
        int s = (sr < 189) ? sr : (1024 + sr - 189);
        p32[(size_t)s * 64 + q] = 0x7C007C00u;
    }
    int fi = cta * 256 + threadIdx.x;
    if (fi < BATCH * NW * 32) g_flag[fi] = 0;
    if (cta == 0 && threadIdx.x == 0) {
        int idx = 0;
        for (int m = 0; m <= 80; m++)
            for (int w = 0; w < 8; w++) {
                int jt = m - 7 * w;
                if (jt >= 0 && jt < 32) g_pairs[idx++] = (unsigned char)(w * 32 + jt);
            }
    }
}

// ---------------------------------------------------------------------------
// Producer unit: 128 threads (4 warps), loops over assigned tiles in the
// DP-consumption order. Same 128x32 tile / 8x4 micro-tile GEMM as before.
// ---------------------------------------------------------------------------
__device__ void producer_part(const float* __restrict__ A, const float* __restrict__ B,
                              float* __restrict__ As, int barid, int unit, int t128) {
    float* Bs = As + 128 * 65;
    const int tx = t128 & 7;
    const int ty = t128 >> 3;

    for (int p = unit; p < NTILES; p += NUNITS) {
        int pr = g_pairs[p >> 5];
        int b = p & 31, w = pr >> 5, jt = pr & 31;
        int j0 = jt * 32;
        const float* Ab = A + ((size_t)b * T + w * 128) * DIM;
        const float* Bb = B + ((size_t)b * T + j0) * DIM;

        for (int v = t128; v < 128 * 16; v += 128) {
            int i = v >> 4, kq = v & 15;
            float4 va = *(const float4*)(Ab + (size_t)i * DIM + kq * 4);
            int base = i * 65 + kq * 4;
            As[base + 0] = va.x; As[base + 1] = va.y; As[base + 2] = va.z; As[base + 3] = va.w;
        }
        for (int v = t128; v < 32 * 16; v += 128) {
            int j = v >> 4, kq = v & 15;
            float4 vb = *(const float4*)(Bb + (size_t)j * DIM + kq * 4);
            int base = j * 65 + kq * 4;
            Bs[base + 0] = vb.x; Bs[base + 1] = vb.y; Bs[base + 2] = vb.z; Bs[base + 3] = vb.w;
        }
        UBAR(barid);

        float acc[8][4];
#pragma unroll
        for (int r = 0; r < 8; r++)
#pragma unroll
            for (int c = 0; c < 4; c++) acc[r][c] = 0.f;

#pragma unroll 4
        for (int k = 0; k < DIM; k++) {
            float ar[8], br[4];
#pragma unroll
            for (int r = 0; r < 8; r++) ar[r] = As[(ty * 8 + r) * 65 + k];
#pragma unroll
            for (int c = 0; c < 4; c++) br[c] = Bs[(tx * 4 + c) * 65 + k];
#pragma unroll
            for (int r = 0; r < 8; r++)
#pragma unroll
                for (int c = 0; c < 4; c++) acc[r][c] += ar[r] * br[c];
        }
        UBAR(barid);                 // As dead; reuse as Ch

        __half* Ch = (__half*)As;    // [128][34]
        {
            float nar[8], nbr[4];
            const float* nap = g_na + b * T + w * 128 + ty * 8;
            const float* nbp = g_nb + b * T + j0 + tx * 4;
#pragma unroll
            for (int r = 0; r < 8; r++) nar[r] = nap[r];
#pragma unroll
            for (int c = 0; c < 4; c++) nbr[c] = nbp[c];
#pragma unroll
            for (int r = 0; r < 8; r++)
#pragma unroll
                for (int c = 0; c < 4; c++) {
                    float sq = nar[r] + nbr[c] - 2.0f * acc[r][c];
                    Ch[(ty * 8 + r) * 34 + (tx * 4 + c)] = __float2half_rn(fmaxf(sq, 1e-12f));
                }
        }
        UBAR(barid);

        // Skewed emit: slot s = j + phi(i); sr = s - j0 in [0, SRMAX).
        const int wid = t128 >> 5, lane = t128 & 31;
        size_t sbase = ((size_t)(b * NW + w) * SPAD + j0) * 128;
#pragma unroll 1
        for (int it = 0; it < 56; it++) {
            int sr = it * 4 + wid;
            if (sr < SRMAX) {
                int aq = sr / 6, bq = sr - 6 * aq;
                int ihi = 4 * aq + (bq < 3 ? bq : 3);
                if (ihi > 127) ihi = 127;
                int i = ihi - 31 + lane;
                if (i >= 0) {
                    int jr = sr - (6 * (i >> 2) + (i & 3));
                    if (jr >= 0 && jr < 32)
                        g_cst[sbase + (size_t)sr * 128 + i] = Ch[i * 34 + jr];
                }
            }
        }
        __threadfence();
        UBAR(barid);
        if (t128 == 0)
            ((volatile int*)g_flag)[(b * NW + w) * 32 + jt] = 1;
    }
}

// ---------------------------------------------------------------------------
// DP part: 8 warps (tids 0..255) of DP CTAs. Same E=2-skew systolic engine;
// chunks additionally gated on producer tile flags.
// ---------------------------------------------------------------------------
__device__ void dp_part(int b, char* smem) {
    unsigned short* hand = (unsigned short*)smem;
    int* progress = (int*)(smem + PROG_OFF);
    const int tid = threadIdx.x, w = tid >> 5, lane = tid & 31;

    for (int v = tid; v < (NW + 1) * HANDW / 2; v += 256)
        ((unsigned*)hand)[v] = 0x7C007C00u;
    if (lane == 0) progress[w] = 0;
    asm volatile("bar.sync 5, 256;" ::: "memory");

    const unsigned short* hrow = &hand[((w == 0) ? NW : (w - 1)) * HANDW];
    unsigned wrow;   // smem addr; +s*2 -> hand[w][s-189]
    {
        unsigned base;
        asm("{ .reg .u64 t; cvta.to.shared.u64 t, %1; cvt.u32.u64 %0, t; }"
            : "=r"(base) : "l"(&hand[w * HANDW]));
        wrow = base - 378u;
    }

    const int fbase = (b * NW + w) * 32;
    {   // wait for level 0 of this strip (preload reads slots 0..31)
        volatile int* f = (volatile int*)&g_flag[fbase];
        while (*f == 0) __nanosleep(128);
    }
    __threadfence();

    const __half* cp = g_cst + (size_t)(b * NW + w) * SPAD * 128 + lane * 4;
    uint2 fA[16], fB[16];
#pragma unroll
    for (int q = 0; q < 16; q++) fA[q] = *(const uint2*)(cp + (size_t)q * 128);
#pragma unroll
    for (int q = 0; q < 16; q++) fB[q] = *(const uint2*)(cp + (size_t)(16 + q) * 128);

    const unsigned INF2 = 0x7C007C00u;
    unsigned A = INF2, B = INF2, upAp = INF2, upBp = INF2;
    unsigned sh0 = INF2, sh1 = INF2;
    unsigned hv0 = INF2, hv1 = INF2, hv2 = INF2;
    const bool isl0 = (lane == 0);
    const bool fix0 = (w == 0) && isl0;
    const unsigned p31 = (lane == 31) ? 1u : 0u;
    const __half* cq = cp;
    int done_lvl = 0;

#define DP_STEP(kk, F, ROFF, FIRST)                                            \
    {                                                                          \
        const int s = sbase + (kk);                                            \
        uint2 cw = F[kk];                                                      \
        F[kk] = *(const uint2*)(cq + (size_t)((kk) + (ROFF)) * 128);           \
        unsigned shu = isl0 ? hv0 : sh0;                                       \
        unsigned upA = __byte_perm(shu, A, 0x5432);                            \
        unsigned upB = __byte_perm(A, B, 0x5432);                              \
        unsigned nA = hmax2u(cw.x, hmin2u(hmin2u(upA, upAp), A));              \
        unsigned nB = hmax2u(cw.y, hmin2u(hmin2u(upB, upBp), B));              \
        if ((FIRST) && (kk) == 0) {                                            \
            if (fix0) nA = (nA & 0xFFFF0000u) | (cw.x & 0xFFFFu);              \
        }                                                                      \
        unsigned pr = p31 & (unsigned)(s >= 189);                              \
        asm volatile(                                                          \
            "{ .reg .pred p; setp.ne.u32 p, %0, 0; @p st.shared.u16 [%1], %2; }" \
            :: "r"(pr), "r"(wrow + (unsigned)s * 2),                           \
               "h"((unsigned short)(nB >> 16)));                               \
        unsigned shn = __shfl_up_sync(0xffffffffu, B, 1);                      \
        sh0 = sh1; sh1 = shn;                                                  \
        upAp = upA; upBp = upB;                                                \
        A = nA; B = nB;                                                        \
        hv0 = hv1; hv1 = hv2;                                                  \
        hv2 = ((unsigned)hrow[s + 3]) << 16;                                   \
    }

    for (int td = 0; td < NCH / 2; td++) {
        {   // gate on producer: chunk td refills read slots <= 32*td+63
            int lvl = td + 1; if (lvl > 31) lvl = 31;
            if (lvl > done_lvl) {
                volatile int* f = (volatile int*)&g_flag[fbase + lvl];
                while (*f == 0) __nanosleep(128);
                __threadfence();
                done_lvl = lvl;
            }
        }
        if (w) {                                 // one wait per 32 steps
            int need = 2 * td + 14; if (need > NCH) need = NCH;
            while (((volatile int*)progress)[w - 1] < need) __nanosleep(32);
            __threadfence_block();
        }
        if (td == 0) {
            hv0 = ((unsigned)hrow[0]) << 16;
            hv1 = ((unsigned)hrow[1]) << 16;
            hv2 = ((unsigned)hrow[2]) << 16;
        }
        {
            const int sbase = 32 * td;
#pragma unroll
            for (int kk = 0; kk < 16; kk++) DP_STEP(kk, fA, 32, (td == 0))
        }
        __syncwarp();
        __threadfence_block();
        if (lane == 0) ((volatile int*)progress)[w] = 2 * td + 1;
        {
            const int sbase = 32 * td + 16;
#pragma unroll
            for (int kk = 0; kk < 16; kk++) DP_STEP(kk, fB, 48, false)
        }
        __syncwarp();
        __threadfence_block();
        if (lane == 0) ((volatile int*)progress)[w] = 2 * td + 2;
        cq += 32 * 128;
    }
#undef DP_STEP

    asm volatile("bar.sync 5, 256;" ::: "memory");
    if (tid == 0)
        g_dists[b] = sqrtf(__half2float(__ushort_as_half(hand[7 * HANDW + 1023])));
}

// ---------------------------------------------------------------------------
// Fused persistent kernel: grid = 148 CTAs (all wave-1 resident).
//   CTA 0..31:  tids 0..255 = DP warps (batch = blockIdx), tids 256..383 =
//               1 producer unit (id 348+cta, barrier 1).
//   CTA 32..147: 3 producer units (ids (cta-32)*3 + {0,1,2}, barriers 1..3).
// ---------------------------------------------------------------------------
__global__ void __launch_bounds__(384, 1) fused_kernel(const float* __restrict__ A,
                                                       const float* __restrict__ B) {
    extern __shared__ char smem[];
    const int cta = blockIdx.x, tid = threadIdx.x;
    if (cta < BATCH) {
        if (tid < 256)
            dp_part(cta, smem);
        else
            producer_part(A, B, (float*)(smem + DPUNIT_OFF), 1, 348 + cta, tid - 256);
    } else {
        int ul = tid >> 7;      // 0..2
        producer_part(A, B, (float*)(smem + ul * UNIT_BYTES), 1 + ul,
                      (cta - 32) * 3 + ul, tid & 127);
    }
}

// ---------------------------------------------------------------------------
__global__ void finish_kernel(float* __restrict__ out) {
    int t = threadIdx.x;
    float v = g_dists[t];
#pragma unroll
    for (int o = 16; o; o >>= 1) v += __shfl_xor_sync(0xffffffffu, v, o);
    if (t == 0) out[0] = v * (1.0f / BATCH);
}

extern "C" void kernel_launch(void* const* d_in, const int* in_sizes, int n_in,
                              void* d_out, int out_size) {
    const float* pred = (const float*)d_in[0];
    const float* targ = (const float*)d_in[1];
    cudaFuncSetAttribute(fused_kernel, cudaFuncAttributeMaxDynamicSharedMemorySize, SMEM_DYN);
    norm_kernel<<<(BATCH * T * 2) / 8, 256>>>(pred, targ);
    fill_kernel<<<BATCH * NW, 256>>>();
    fused_kernel<<<148, 384, SMEM_DYN>>>(pred, targ);
    finish_kernel<<<1, 32>>>((float*)d_out);
}